// round 6
// baseline (speedup 1.0000x reference)
#include <cuda_runtime.h>
#include <cuda_bf16.h>
#include <cstdint>

#define L 4096
#define DE 1024
#define DV 1024
#define HEXP 0.2f
#define DTF (1.0f / 4096.0f)
#define EPSV 1e-8f
#define FFT_N 8192

// ---------------- device scratch (static, no runtime alloc) ----------------
__device__ __nv_bfloat16 g_Et_hi[L * DE];   // E^T hi  ([l][e], e contiguous)
__device__ __nv_bfloat16 g_Et_lo[L * DE];
__device__ __nv_bfloat16 g_W_hi[DV * DE];   // W  ([v][e], e contiguous)
__device__ __nv_bfloat16 g_W_lo[DV * DE];
__device__ float g_Yt[(size_t)DV * L];      // Y^T fp32 ([v][l], l contiguous)
__device__ float g_outT[(size_t)DV * L];    // conv result [c][i]
__device__ float2 g_tw[FFT_N];              // exp(-2*pi*i*n/N), full table (for W^{3u})
__device__ float2 g_F[FFT_N];               // FFT(f_padded)/N

// ---------------- helpers ---------------------------------------------------
__device__ __forceinline__ uint32_t smem_u32(const void* p) {
    uint32_t a;
    asm("{ .reg .u64 t; cvta.to.shared.u64 t, %1; cvt.u32.u64 %0, t; }" : "=r"(a) : "l"(p));
    return a;
}
#define SW64(o) ((uint32_t)(o) ^ ((((uint32_t)(o)) >> 3) & 0x30u))

__device__ __forceinline__ void cpasync16(uint32_t dst, const void* src) {
    asm volatile("cp.async.cg.shared.global [%0], [%1], 16;" :: "r"(dst), "l"(src));
}
#define CP_COMMIT() asm volatile("cp.async.commit_group;" ::: "memory")
#define CP_WAIT2()  asm volatile("cp.async.wait_group 2;" ::: "memory")

__device__ __forceinline__ void ldsm4(uint32_t* r, uint32_t addr) {
    asm volatile("ldmatrix.sync.aligned.m8n8.x4.shared.b16 {%0,%1,%2,%3}, [%4];"
                 : "=r"(r[0]), "=r"(r[1]), "=r"(r[2]), "=r"(r[3]) : "r"(addr));
}
__device__ __forceinline__ void mma_bf16(float* c, const uint32_t* a, const uint32_t* b) {
    asm volatile(
        "mma.sync.aligned.m16n8k16.row.col.f32.bf16.bf16.f32 "
        "{%0,%1,%2,%3}, {%4,%5,%6,%7}, {%8,%9}, {%0,%1,%2,%3};"
        : "+f"(c[0]), "+f"(c[1]), "+f"(c[2]), "+f"(c[3])
        : "r"(a[0]), "r"(a[1]), "r"(a[2]), "r"(a[3]), "r"(b[0]), "r"(b[1]));
}

__device__ __forceinline__ float2 cmul(float2 a, float2 b) {
    return make_float2(a.x * b.x - a.y * b.y, a.x * b.y + a.y * b.x);
}
__device__ __forceinline__ float2 cadd(float2 a, float2 b) { return make_float2(a.x + b.x, a.y + b.y); }
__device__ __forceinline__ float2 csub(float2 a, float2 b) { return make_float2(a.x - b.x, a.y - b.y); }

// ---------------- GEMM tiling: CTA 128(m) x 256(n), warp 64x64, BK=32 -------
// Per stage: Ahi(8K) Alo(8K) Bhi(16K) Blo(16K) = 48KB.  3 stages = 144KB.
#define STAGE_BYTES 49152
#define T_AHI 0
#define T_ALO 8192
#define T_BHI 16384
#define T_BLO 32768
#define GEMM_SMEM (3 * STAGE_BYTES)

// fill rows x 32 bf16 k-major tile via cp.async; ITERS = rows*4/256
template <int ITERS>
__device__ __forceinline__ void fill_tile32(uint32_t dstbase,
                                            const __nv_bfloat16* __restrict__ g,
                                            int row0, int k0, int stride, int tid) {
#pragma unroll
    for (int i = 0; i < ITERS; ++i) {
        int q = tid + i * 256;
        int r = q >> 2, c = q & 3;
        uint32_t o = (uint32_t)(r * 64 + c * 16);
        cpasync16(dstbase + SW64(o), g + (size_t)(row0 + r) * stride + k0 + c * 8);
    }
}

// ---------------- pre-kernels -----------------------------------------------
__global__ void init_tw_kernel() {
    int n = blockIdx.x * 256 + threadIdx.x;
    if (n < FFT_N) {
        float s, c;
        sincospif(-2.0f * (float)n / (float)FFT_N, &s, &c);
        g_tw[n] = make_float2(c, s);
    }
}

__global__ void transpose_E_kernel(const float* __restrict__ E) {
    __shared__ float t[32][33];
    int bx = blockIdx.x, by = blockIdx.y;
    int tx = threadIdx.x, ty = threadIdx.y;      // block (32, 8)
#pragma unroll
    for (int i = 0; i < 4; ++i)
        t[ty + 8 * i][tx] = E[(size_t)(by * 32 + ty + 8 * i) * L + bx * 32 + tx];
    __syncthreads();
#pragma unroll
    for (int i = 0; i < 4; ++i) {
        float v = t[tx][ty + 8 * i];
        size_t o = (size_t)(bx * 32 + ty + 8 * i) * DE + by * 32 + tx;
        __nv_bfloat16 hi = __float2bfloat16(v);
        g_Et_hi[o] = hi;
        g_Et_lo[o] = __float2bfloat16(v - __bfloat162float(hi));
    }
}

__global__ void convert_W_kernel(const float* __restrict__ W) {
    int i = blockIdx.x * blockDim.x + threadIdx.x;
#pragma unroll
    for (int u = 0; u < 4; ++u) {
        int idx = i * 4 + u;
        float v = W[idx];
        __nv_bfloat16 hi = __float2bfloat16(v);
        g_W_hi[idx] = hi;
        g_W_lo[idx] = __float2bfloat16(v - __bfloat162float(hi));
    }
}

// ---------------- radix-4 Stockham FFT (6 r4 stages + 1 r2 stage) ------------
// Reads src0; result lands in dst0 after 7 stage-passes.
template <int MULT_F>
__device__ __forceinline__ void fft_stages4(float2* src0, float2* dst0, int tid, int inv) {
    float2* src = src0;
    float2* dst = dst0;
    int m = 1;
#pragma unroll 1
    for (int s = 0; s < 6; ++s) {
#pragma unroll
        for (int it = 0; it < 8; ++it) {
            int bf = tid + (it << 8);            // 0..2047
            int k = bf & (m - 1);
            int u = bf - k;                      // q*m
            float2 x0 = src[bf];
            float2 x1 = src[bf + FFT_N / 4];
            float2 x2 = src[bf + FFT_N / 2];
            float2 x3 = src[bf + 3 * (FFT_N / 4)];
            float2 t0 = cadd(x0, x2);
            float2 t1 = csub(x0, x2);
            float2 t2 = cadd(x1, x3);
            float2 t3 = csub(x1, x3);
            float2 jt3 = inv ? make_float2(-t3.y, t3.x) : make_float2(t3.y, -t3.x);
            float2 w1 = g_tw[u];
            float2 w2 = g_tw[2 * u];
            float2 w3 = g_tw[3 * u];
            if (inv) { w1.y = -w1.y; w2.y = -w2.y; w3.y = -w3.y; }
            int b4 = 4 * u + k;
            dst[b4]         = cadd(t0, t2);
            dst[b4 + m]     = cmul(w1, cadd(t1, jt3));
            dst[b4 + 2 * m] = cmul(w2, csub(t0, t2));
            dst[b4 + 3 * m] = cmul(w3, csub(t1, jt3));
        }
        __syncthreads();
        float2* t = src; src = dst; dst = t;
        m <<= 2;
    }
    // final radix-2 stage: m = 4096, twiddle = 1 (optionally x F[n] on write)
#pragma unroll
    for (int it = 0; it < 16; ++it) {
        int k = tid + (it << 8);                 // 0..4095
        float2 a = src[k];
        float2 b = src[k + FFT_N / 2];
        float2 lo = cadd(a, b);
        float2 hi = csub(a, b);
        if (MULT_F) {
            lo = cmul(lo, g_F[k]);
            hi = cmul(hi, g_F[k + FFT_N / 2]);
        }
        dst[k] = lo;
        dst[k + FFT_N / 2] = hi;
    }
    __syncthreads();
}

// F = FFT(f_padded) / N   (single CTA)
__global__ __launch_bounds__(256) void fft_F_kernel() {
    extern __shared__ float2 sm[];
    float2* A = sm;
    float2* B = sm + FFT_N;
    int tid = threadIdx.x;
#pragma unroll
    for (int it = 0; it < 32; ++it) {
        int d = tid + it * 256;
        float v = 0.f;
        if (d < L) {
            float base = (d == 0) ? EPSV : ((float)d * DTF + EPSV);
            v = powf(base, HEXP);
        }
        A[d] = make_float2(v, 0.f);
    }
    __syncthreads();
    fft_stages4<0>(A, B, tid, 0);
    const float scale = 1.0f / (float)FFT_N;
#pragma unroll
    for (int it = 0; it < 32; ++it) {
        int n = tid + it * 256;
        g_F[n] = make_float2(B[n].x * scale, B[n].y * scale);
    }
}

// Causal conv via FFT: channels (2c, 2c+1) packed as Re/Im of one complex seq.
__global__ __launch_bounds__(256) void conv_kernel() {
    extern __shared__ float2 sm[];
    float2* A = sm;
    float2* B = sm + FFT_N;
    int tid = threadIdx.x;
    int c2 = blockIdx.x * 2;
    const float* ya = g_Yt + (size_t)c2 * L;
    const float* yb = g_Yt + (size_t)(c2 + 1) * L;
#pragma unroll
    for (int it = 0; it < 16; ++it) {
        int i = tid + it * 256;
        A[i] = make_float2(ya[i], yb[i]);
    }
#pragma unroll
    for (int it = 0; it < 16; ++it) {
        int i = L + tid + it * 256;
        A[i] = make_float2(0.f, 0.f);
    }
    __syncthreads();
    fft_stages4<1>(A, B, tid, 0);      // forward + pointwise x F fused, result in B
    fft_stages4<0>(B, A, tid, 1);      // inverse (1/N folded into F), result in A
    float* oa = g_outT + (size_t)c2 * L;
    float* ob = g_outT + (size_t)(c2 + 1) * L;
#pragma unroll
    for (int it = 0; it < 16; ++it) {
        int i = tid + it * 256;
        float2 z = A[i];
        oa[i] = z.x;
        ob[i] = z.y;
    }
}

// g_outT [c][i] -> out [i][c]
__global__ void transpose_out_kernel(float* __restrict__ out) {
    __shared__ float t[32][33];
    int i0 = blockIdx.x * 32, c0 = blockIdx.y * 32;
    int tx = threadIdx.x, ty = threadIdx.y;  // (32, 8)
#pragma unroll
    for (int k = 0; k < 4; ++k)
        t[ty + 8 * k][tx] = g_outT[(size_t)(c0 + ty + 8 * k) * L + i0 + tx];
    __syncthreads();
#pragma unroll
    for (int k = 0; k < 4; ++k)
        out[(size_t)(i0 + ty + 8 * k) * DV + c0 + tx] = t[tx][ty + 8 * k];
}

// ---------------- GEMM1 compute core: warp tile 64x64 -----------------------
__device__ __forceinline__ void compute_stage64(uint32_t sbase, int lane, int wm, int wn,
                                                float acc[4][8][4]) {
    const int arow = lane & 15;
    const int acolb = (lane >> 4) << 4;
    const int brow = (lane & 7) + ((lane >> 4) << 3);
    const int bcolb = ((lane >> 3) & 1) << 4;
#pragma unroll
    for (int kk = 0; kk < 2; ++kk) {
        uint32_t aH[4][4], aL[4][4];
#pragma unroll
        for (int mi = 0; mi < 4; ++mi) {
            uint32_t o = SW64((uint32_t)((wm * 64 + mi * 16 + arow) * 64 + acolb)) ^ (kk << 5);
            ldsm4(aH[mi], sbase + T_AHI + o);
            ldsm4(aL[mi], sbase + T_ALO + o);
        }
#pragma unroll
        for (int pi = 0; pi < 4; ++pi) {
            uint32_t bH[4], bL[4];
            uint32_t o = SW64((uint32_t)((wn * 64 + pi * 16 + brow) * 64 + bcolb)) ^ (kk << 5);
            ldsm4(bH, sbase + T_BHI + o);
            ldsm4(bL, sbase + T_BLO + o);
#pragma unroll
            for (int mi = 0; mi < 4; ++mi)
#pragma unroll
                for (int q = 0; q < 2; ++q) {
                    mma_bf16(acc[mi][pi * 2 + q], aH[mi], &bH[q * 2]);
                    mma_bf16(acc[mi][pi * 2 + q], aH[mi], &bL[q * 2]);
                    mma_bf16(acc[mi][pi * 2 + q], aL[mi], &bH[q * 2]);
                }
        }
    }
}

// ---------------- GEMM1: Yt[v][l] = sum_e W[v][e] * Et[l][e] ----------------
// m = v (A = W, 128), n = l (B = Et, 256), k = e.
__global__ __launch_bounds__(256) void gemm1_mma() {
    extern __shared__ char smem[];
    const uint32_t sb = smem_u32(smem);
    const int tid = threadIdx.x, lane = tid & 31, wid = tid >> 5;
    const int wm = wid & 1, wn = wid >> 1;
    const int l0 = blockIdx.x * 256;   // n
    const int v0 = blockIdx.y * 128;   // m
    const int KT = DE / 32;

    float acc[4][8][4];
#pragma unroll
    for (int mi = 0; mi < 4; ++mi)
#pragma unroll
        for (int ni = 0; ni < 8; ++ni)
#pragma unroll
            for (int r = 0; r < 4; ++r) acc[mi][ni][r] = 0.f;

#pragma unroll
    for (int s = 0; s < 2; ++s) {
        uint32_t st = sb + s * STAGE_BYTES;
        int k0 = s * 32;
        fill_tile32<2>(st + T_AHI, g_W_hi, v0, k0, DE, tid);
        fill_tile32<2>(st + T_ALO, g_W_lo, v0, k0, DE, tid);
        fill_tile32<4>(st + T_BHI, g_Et_hi, l0, k0, DE, tid);
        fill_tile32<4>(st + T_BLO, g_Et_lo, l0, k0, DE, tid);
        CP_COMMIT();
    }
    for (int kt = 0; kt < KT; ++kt) {
        int ls = kt + 2;
        if (ls < KT) {
            uint32_t st = sb + (ls % 3) * STAGE_BYTES;
            int k0 = ls * 32;
            fill_tile32<2>(st + T_AHI, g_W_hi, v0, k0, DE, tid);
            fill_tile32<2>(st + T_ALO, g_W_lo, v0, k0, DE, tid);
            fill_tile32<4>(st + T_BHI, g_Et_hi, l0, k0, DE, tid);
            fill_tile32<4>(st + T_BLO, g_Et_lo, l0, k0, DE, tid);
        }
        CP_COMMIT();
        CP_WAIT2();
        __syncthreads();
        compute_stage64(sb + (kt % 3) * STAGE_BYTES, lane, wm, wn, acc);
        __syncthreads();
    }

    // epilogue: D[m=v][n=l] -> g_Yt fp32
#pragma unroll
    for (int mi = 0; mi < 4; ++mi)
#pragma unroll
        for (int ni = 0; ni < 8; ++ni) {
            const float* c = acc[mi][ni];
            int v_ = v0 + wm * 64 + mi * 16 + (lane >> 2);
            int l_ = l0 + wn * 64 + ni * 8 + 2 * (lane & 3);
#pragma unroll
            for (int h = 0; h < 2; ++h) {
                float2 p;
                p.x = c[2 * h];
                p.y = c[2 * h + 1];
                *reinterpret_cast<float2*>(&g_Yt[(size_t)(v_ + 8 * h) * L + l_]) = p;
            }
        }
}

// ---------------------------------------------------------------------------
#define FFT_SMEM (2 * FFT_N * (int)sizeof(float2))

extern "C" void kernel_launch(void* const* d_in, const int* in_sizes, int n_in,
                              void* d_out, int out_size) {
    const float* E = (const float*)d_in[0];   // (1024, 4096)
    const float* W = (const float*)d_in[1];   // (1024, 1024)
    float* out = (float*)d_out;               // (4096, 1024)

    cudaFuncSetAttribute(gemm1_mma, cudaFuncAttributeMaxDynamicSharedMemorySize, GEMM_SMEM);
    cudaFuncSetAttribute(fft_F_kernel, cudaFuncAttributeMaxDynamicSharedMemorySize, FFT_SMEM);
    cudaFuncSetAttribute(conv_kernel, cudaFuncAttributeMaxDynamicSharedMemorySize, FFT_SMEM);

    init_tw_kernel<<<FFT_N / 256, 256>>>();
    fft_F_kernel<<<1, 256, FFT_SMEM>>>();
    transpose_E_kernel<<<dim3(L / 32, DE / 32), dim3(32, 8)>>>(E);
    convert_W_kernel<<<(DV * DE) / 1024, 256>>>(W);
    gemm1_mma<<<dim3(L / 256, DV / 128), 256, GEMM_SMEM>>>();
    conv_kernel<<<DV / 2, 256, FFT_SMEM>>>();
    transpose_out_kernel<<<dim3(L / 32, DV / 32), dim3(32, 8)>>>(out);
}

// round 7
// speedup vs baseline: 1.1262x; 1.1262x over previous
#include <cuda_runtime.h>
#include <cuda_bf16.h>
#include <cstdint>

#define L 4096
#define DE 1024
#define DV 1024
#define HEXP 0.2f
#define DTF (1.0f / 4096.0f)
#define EPSV 1e-8f
#define FFT_N 8192

// ---------------- device scratch (static, no runtime alloc) ----------------
__device__ __nv_bfloat16 g_Et_hi[L * DE];   // E^T hi  ([l][e], e contiguous)
__device__ __nv_bfloat16 g_Et_lo[L * DE];
__device__ __nv_bfloat16 g_W_hi[DV * DE];   // W  ([v][e], e contiguous)
__device__ __nv_bfloat16 g_W_lo[DV * DE];
__device__ float g_Yt[(size_t)DV * L];      // Y^T fp32 ([v][l], l contiguous)
__device__ float g_outT[(size_t)DV * L];    // conv result [c][i]
__device__ float2 g_tw[FFT_N];              // exp(-2*pi*i*n/N), full table (W^{7u} max)
__device__ float2 g_F[FFT_N];               // FFT(f_padded)/N

// ---------------- helpers ---------------------------------------------------
__device__ __forceinline__ uint32_t smem_u32(const void* p) {
    uint32_t a;
    asm("{ .reg .u64 t; cvta.to.shared.u64 t, %1; cvt.u32.u64 %0, t; }" : "=r"(a) : "l"(p));
    return a;
}
#define SW64(o) ((uint32_t)(o) ^ ((((uint32_t)(o)) >> 3) & 0x30u))

__device__ __forceinline__ void cpasync16(uint32_t dst, const void* src) {
    asm volatile("cp.async.cg.shared.global [%0], [%1], 16;" :: "r"(dst), "l"(src));
}
#define CP_COMMIT() asm volatile("cp.async.commit_group;" ::: "memory")
#define CP_WAIT2()  asm volatile("cp.async.wait_group 2;" ::: "memory")

__device__ __forceinline__ void ldsm4(uint32_t* r, uint32_t addr) {
    asm volatile("ldmatrix.sync.aligned.m8n8.x4.shared.b16 {%0,%1,%2,%3}, [%4];"
                 : "=r"(r[0]), "=r"(r[1]), "=r"(r[2]), "=r"(r[3]) : "r"(addr));
}
__device__ __forceinline__ void mma_bf16(float* c, const uint32_t* a, const uint32_t* b) {
    asm volatile(
        "mma.sync.aligned.m16n8k16.row.col.f32.bf16.bf16.f32 "
        "{%0,%1,%2,%3}, {%4,%5,%6,%7}, {%8,%9}, {%0,%1,%2,%3};"
        : "+f"(c[0]), "+f"(c[1]), "+f"(c[2]), "+f"(c[3])
        : "r"(a[0]), "r"(a[1]), "r"(a[2]), "r"(a[3]), "r"(b[0]), "r"(b[1]));
}

__device__ __forceinline__ float2 cmul(float2 a, float2 b) {
    return make_float2(a.x * b.x - a.y * b.y, a.x * b.y + a.y * b.x);
}
__device__ __forceinline__ float2 cadd(float2 a, float2 b) { return make_float2(a.x + b.x, a.y + b.y); }
__device__ __forceinline__ float2 csub(float2 a, float2 b) { return make_float2(a.x - b.x, a.y - b.y); }

// ---------------- GEMM tiling: CTA 128x128, 4 warps (64x64 each), BK=32 -----
// Per stage: Ahi(8K) Alo(8K) Bhi(8K) Blo(8K) = 32KB.  3 stages = 96KB.
#define STAGE_BYTES 32768
#define T_AHI 0
#define T_ALO 8192
#define T_BHI 16384
#define T_BLO 24576
#define GEMM_SMEM (3 * STAGE_BYTES)

// fill 128x32 bf16 k-major tile via cp.async; 128 threads, 4 iters
__device__ __forceinline__ void fill_tile32(uint32_t dstbase,
                                            const __nv_bfloat16* __restrict__ g,
                                            int row0, int k0, int stride, int tid) {
#pragma unroll
    for (int i = 0; i < 4; ++i) {
        int q = tid + i * 128;
        int r = q >> 2, c = q & 3;
        uint32_t o = (uint32_t)(r * 64 + c * 16);
        cpasync16(dstbase + SW64(o), g + (size_t)(row0 + r) * stride + k0 + c * 8);
    }
}

// ---------------- pre-kernels -----------------------------------------------
__global__ void init_tw_kernel() {
    int n = blockIdx.x * 256 + threadIdx.x;
    if (n < FFT_N) {
        float s, c;
        sincospif(-2.0f * (float)n / (float)FFT_N, &s, &c);
        g_tw[n] = make_float2(c, s);
    }
}

__global__ void transpose_E_kernel(const float* __restrict__ E) {
    __shared__ float t[32][33];
    int bx = blockIdx.x, by = blockIdx.y;
    int tx = threadIdx.x, ty = threadIdx.y;      // block (32, 8)
#pragma unroll
    for (int i = 0; i < 4; ++i)
        t[ty + 8 * i][tx] = E[(size_t)(by * 32 + ty + 8 * i) * L + bx * 32 + tx];
    __syncthreads();
#pragma unroll
    for (int i = 0; i < 4; ++i) {
        float v = t[tx][ty + 8 * i];
        size_t o = (size_t)(bx * 32 + ty + 8 * i) * DE + by * 32 + tx;
        __nv_bfloat16 hi = __float2bfloat16(v);
        g_Et_hi[o] = hi;
        g_Et_lo[o] = __float2bfloat16(v - __bfloat162float(hi));
    }
}

__global__ void convert_W_kernel(const float* __restrict__ W) {
    int i = blockIdx.x * blockDim.x + threadIdx.x;
#pragma unroll
    for (int u = 0; u < 4; ++u) {
        int idx = i * 4 + u;
        float v = W[idx];
        __nv_bfloat16 hi = __float2bfloat16(v);
        g_W_hi[idx] = hi;
        g_W_lo[idx] = __float2bfloat16(v - __bfloat162float(hi));
    }
}

// ---------------- radix-8 Stockham FFT, skewed smem --------------------------
// PHY: bank-conflict skew (bijective monotone map); applied to ALL smem refs.
#define PHY(i) ((i) + ((i) >> 4))
#define FFT_BUF 8704                         // PHY(8191)=8702 < 8704
#define C_SQ2 0.70710678118654752f

// 4 radix-8 stages + 1 radix-2 stage = 5 passes; result lands in dst0.
template <int MULT_F, int INV>
__device__ __forceinline__ void fft_stages8(float2* src0, float2* dst0, int tid) {
    float2* src = src0;
    float2* dst = dst0;
    int m = 1;
#pragma unroll 1
    for (int s = 0; s < 4; ++s) {
#pragma unroll
        for (int it = 0; it < 4; ++it) {
            int bf = tid + (it << 8);            // 0..1023
            int k = bf & (m - 1);
            int u = bf - k;                      // multiple of m
            float2 x0 = src[PHY(bf)];
            float2 x1 = src[PHY(bf + 1024)];
            float2 x2 = src[PHY(bf + 2048)];
            float2 x3 = src[PHY(bf + 3072)];
            float2 x4 = src[PHY(bf + 4096)];
            float2 x5 = src[PHY(bf + 5120)];
            float2 x6 = src[PHY(bf + 6144)];
            float2 x7 = src[PHY(bf + 7168)];
            // DFT8 (even/odd DFT4 + combine), mj = -i (fwd) / +i (inv)
            float2 t0 = cadd(x0, x4), t1 = csub(x0, x4);
            float2 t2 = cadd(x2, x6), t3 = csub(x2, x6);
            float2 s0 = cadd(x1, x5), s1 = csub(x1, x5);
            float2 s2 = cadd(x3, x7), s3 = csub(x3, x7);
            float2 mjt3 = INV ? make_float2(-t3.y, t3.x) : make_float2(t3.y, -t3.x);
            float2 mjs3 = INV ? make_float2(-s3.y, s3.x) : make_float2(s3.y, -s3.x);
            float2 E0 = cadd(t0, t2), E2 = csub(t0, t2);
            float2 E1 = cadd(t1, mjt3), E3 = csub(t1, mjt3);
            float2 O0 = cadd(s0, s2), O2 = csub(s0, s2);
            float2 O1 = cadd(s1, mjs3), O3 = csub(s1, mjs3);
            // omega8^j factors on O_j
            float2 w1O1 = INV ? make_float2(C_SQ2 * (O1.x - O1.y), C_SQ2 * (O1.x + O1.y))
                              : make_float2(C_SQ2 * (O1.x + O1.y), C_SQ2 * (O1.y - O1.x));
            float2 w2O2 = INV ? make_float2(-O2.y, O2.x) : make_float2(O2.y, -O2.x);
            float2 w3O3 = INV ? make_float2(-C_SQ2 * (O3.x + O3.y), C_SQ2 * (O3.x - O3.y))
                              : make_float2(C_SQ2 * (O3.y - O3.x), -C_SQ2 * (O3.x + O3.y));
            float2 X[8];
            X[0] = cadd(E0, O0);   X[4] = csub(E0, O0);
            X[1] = cadd(E1, w1O1); X[5] = csub(E1, w1O1);
            X[2] = cadd(E2, w2O2); X[6] = csub(E2, w2O2);
            X[3] = cadd(E3, w3O3); X[7] = csub(E3, w3O3);
            int b8 = 8 * u + k;
            dst[PHY(b8)] = X[0];
#pragma unroll
            for (int j = 1; j < 8; ++j) {
                float2 w = g_tw[j * u];
                if (INV) w.y = -w.y;
                dst[PHY(b8 + j * m)] = cmul(w, X[j]);
            }
        }
        __syncthreads();
        float2* t = src; src = dst; dst = t;
        m <<= 3;
    }
    // final radix-2 stage: m = 4096, twiddle = 1 (optionally x F[n] on write)
#pragma unroll
    for (int it = 0; it < 16; ++it) {
        int k = tid + (it << 8);                 // 0..4095
        float2 a = src[PHY(k)];
        float2 b = src[PHY(k + FFT_N / 2)];
        float2 lo = cadd(a, b);
        float2 hi = csub(a, b);
        if (MULT_F) {
            lo = cmul(lo, g_F[k]);
            hi = cmul(hi, g_F[k + FFT_N / 2]);
        }
        dst[PHY(k)] = lo;
        dst[PHY(k + FFT_N / 2)] = hi;
    }
    __syncthreads();
}

// F = FFT(f_padded) / N   (single CTA)
__global__ __launch_bounds__(256) void fft_F_kernel() {
    extern __shared__ float2 sm[];
    float2* A = sm;
    float2* B = sm + FFT_BUF;
    int tid = threadIdx.x;
#pragma unroll
    for (int it = 0; it < 32; ++it) {
        int d = tid + it * 256;
        float v = 0.f;
        if (d < L) {
            float base = (d == 0) ? EPSV : ((float)d * DTF + EPSV);
            v = powf(base, HEXP);
        }
        A[PHY(d)] = make_float2(v, 0.f);
    }
    __syncthreads();
    fft_stages8<0, 0>(A, B, tid);
    const float scale = 1.0f / (float)FFT_N;
#pragma unroll
    for (int it = 0; it < 32; ++it) {
        int n = tid + it * 256;
        float2 z = B[PHY(n)];
        g_F[n] = make_float2(z.x * scale, z.y * scale);
    }
}

// Causal conv via FFT: channels (2c, 2c+1) packed as Re/Im of one complex seq.
__global__ __launch_bounds__(256) void conv_kernel() {
    extern __shared__ float2 sm[];
    float2* A = sm;
    float2* B = sm + FFT_BUF;
    int tid = threadIdx.x;
    int c2 = blockIdx.x * 2;
    const float* ya = g_Yt + (size_t)c2 * L;
    const float* yb = g_Yt + (size_t)(c2 + 1) * L;
#pragma unroll
    for (int it = 0; it < 16; ++it) {
        int i = tid + it * 256;
        A[PHY(i)] = make_float2(ya[i], yb[i]);
    }
#pragma unroll
    for (int it = 0; it < 16; ++it) {
        int i = L + tid + it * 256;
        A[PHY(i)] = make_float2(0.f, 0.f);
    }
    __syncthreads();
    fft_stages8<1, 0>(A, B, tid);      // forward + pointwise x F fused -> B
    fft_stages8<0, 1>(B, A, tid);      // inverse (1/N folded into F)   -> A
    float* oa = g_outT + (size_t)c2 * L;
    float* ob = g_outT + (size_t)(c2 + 1) * L;
#pragma unroll
    for (int it = 0; it < 16; ++it) {
        int i = tid + it * 256;
        float2 z = A[PHY(i)];
        oa[i] = z.x;
        ob[i] = z.y;
    }
}

// g_outT [c][i] -> out [i][c]
__global__ void transpose_out_kernel(float* __restrict__ out) {
    __shared__ float t[32][33];
    int i0 = blockIdx.x * 32, c0 = blockIdx.y * 32;
    int tx = threadIdx.x, ty = threadIdx.y;  // (32, 8)
#pragma unroll
    for (int k = 0; k < 4; ++k)
        t[ty + 8 * k][tx] = g_outT[(size_t)(c0 + ty + 8 * k) * L + i0 + tx];
    __syncthreads();
#pragma unroll
    for (int k = 0; k < 4; ++k)
        out[(size_t)(i0 + ty + 8 * k) * DV + c0 + tx] = t[tx][ty + 8 * k];
}

// ---------------- GEMM1 compute core: warp tile 64x64 -----------------------
__device__ __forceinline__ void compute_stage64(uint32_t sbase, int lane, int wm, int wn,
                                                float acc[4][8][4]) {
    const int arow = lane & 15;
    const int acolb = (lane >> 4) << 4;
    const int brow = (lane & 7) + ((lane >> 4) << 3);
    const int bcolb = ((lane >> 3) & 1) << 4;
#pragma unroll
    for (int kk = 0; kk < 2; ++kk) {
        uint32_t aH[4][4], aL[4][4];
#pragma unroll
        for (int mi = 0; mi < 4; ++mi) {
            uint32_t o = SW64((uint32_t)((wm * 64 + mi * 16 + arow) * 64 + acolb)) ^ (kk << 5);
            ldsm4(aH[mi], sbase + T_AHI + o);
            ldsm4(aL[mi], sbase + T_ALO + o);
        }
#pragma unroll
        for (int pi = 0; pi < 4; ++pi) {
            uint32_t bH[4], bL[4];
            uint32_t o = SW64((uint32_t)((wn * 64 + pi * 16 + brow) * 64 + bcolb)) ^ (kk << 5);
            ldsm4(bH, sbase + T_BHI + o);
            ldsm4(bL, sbase + T_BLO + o);
#pragma unroll
            for (int mi = 0; mi < 4; ++mi)
#pragma unroll
                for (int q = 0; q < 2; ++q) {
                    mma_bf16(acc[mi][pi * 2 + q], aH[mi], &bH[q * 2]);
                    mma_bf16(acc[mi][pi * 2 + q], aH[mi], &bL[q * 2]);
                    mma_bf16(acc[mi][pi * 2 + q], aL[mi], &bH[q * 2]);
                }
        }
    }
}

// ---------------- GEMM1: Yt[v][l] = sum_e W[v][e] * Et[l][e] ----------------
// m = v (A = W, 128), n = l (B = Et, 128), k = e.  128 threads, 2 CTAs/SM.
__global__ __launch_bounds__(128, 2) void gemm1_mma() {
    extern __shared__ char smem[];
    const uint32_t sb = smem_u32(smem);
    const int tid = threadIdx.x, lane = tid & 31, wid = tid >> 5;
    const int wm = wid & 1, wn = (wid >> 1) & 1;
    const int l0 = blockIdx.x * 128;   // n
    const int v0 = blockIdx.y * 128;   // m
    const int KT = DE / 32;

    float acc[4][8][4];
#pragma unroll
    for (int mi = 0; mi < 4; ++mi)
#pragma unroll
        for (int ni = 0; ni < 8; ++ni)
#pragma unroll
            for (int r = 0; r < 4; ++r) acc[mi][ni][r] = 0.f;

#pragma unroll
    for (int s = 0; s < 2; ++s) {
        uint32_t st = sb + s * STAGE_BYTES;
        int k0 = s * 32;
        fill_tile32(st + T_AHI, g_W_hi, v0, k0, DE, tid);
        fill_tile32(st + T_ALO, g_W_lo, v0, k0, DE, tid);
        fill_tile32(st + T_BHI, g_Et_hi, l0, k0, DE, tid);
        fill_tile32(st + T_BLO, g_Et_lo, l0, k0, DE, tid);
        CP_COMMIT();
    }
    for (int kt = 0; kt < KT; ++kt) {
        int ls = kt + 2;
        if (ls < KT) {
            uint32_t st = sb + (ls % 3) * STAGE_BYTES;
            int k0 = ls * 32;
            fill_tile32(st + T_AHI, g_W_hi, v0, k0, DE, tid);
            fill_tile32(st + T_ALO, g_W_lo, v0, k0, DE, tid);
            fill_tile32(st + T_BHI, g_Et_hi, l0, k0, DE, tid);
            fill_tile32(st + T_BLO, g_Et_lo, l0, k0, DE, tid);
        }
        CP_COMMIT();
        CP_WAIT2();
        __syncthreads();
        compute_stage64(sb + (kt % 3) * STAGE_BYTES, lane, wm, wn, acc);
        __syncthreads();
    }

    // epilogue: D[m=v][n=l] -> g_Yt fp32
#pragma unroll
    for (int mi = 0; mi < 4; ++mi)
#pragma unroll
        for (int ni = 0; ni < 8; ++ni) {
            const float* c = acc[mi][ni];
            int v_ = v0 + wm * 64 + mi * 16 + (lane >> 2);
            int l_ = l0 + wn * 64 + ni * 8 + 2 * (lane & 3);
#pragma unroll
            for (int h = 0; h < 2; ++h) {
                float2 p;
                p.x = c[2 * h];
                p.y = c[2 * h + 1];
                *reinterpret_cast<float2*>(&g_Yt[(size_t)(v_ + 8 * h) * L + l_]) = p;
            }
        }
}

// ---------------------------------------------------------------------------
#define FFT_SMEM (2 * FFT_BUF * (int)sizeof(float2))

extern "C" void kernel_launch(void* const* d_in, const int* in_sizes, int n_in,
                              void* d_out, int out_size) {
    const float* E = (const float*)d_in[0];   // (1024, 4096)
    const float* W = (const float*)d_in[1];   // (1024, 1024)
    float* out = (float*)d_out;               // (4096, 1024)

    cudaFuncSetAttribute(gemm1_mma, cudaFuncAttributeMaxDynamicSharedMemorySize, GEMM_SMEM);
    cudaFuncSetAttribute(fft_F_kernel, cudaFuncAttributeMaxDynamicSharedMemorySize, FFT_SMEM);
    cudaFuncSetAttribute(conv_kernel, cudaFuncAttributeMaxDynamicSharedMemorySize, FFT_SMEM);

    init_tw_kernel<<<FFT_N / 256, 256>>>();
    fft_F_kernel<<<1, 256, FFT_SMEM>>>();
    transpose_E_kernel<<<dim3(L / 32, DE / 32), dim3(32, 8)>>>(E);
    convert_W_kernel<<<(DV * DE) / 1024, 256>>>(W);
    gemm1_mma<<<dim3(L / 128, DV / 128), 128, GEMM_SMEM>>>();
    conv_kernel<<<DV / 2, 256, FFT_SMEM>>>();
    transpose_out_kernel<<<dim3(L / 32, DV / 32), dim3(32, 8)>>>(out);
}

// round 8
// speedup vs baseline: 1.1903x; 1.0569x over previous
#include <cuda_runtime.h>
#include <cuda_bf16.h>
#include <cstdint>

#define L 4096
#define DE 1024
#define DV 1024
#define HEXP 0.2f
#define DTF (1.0f / 4096.0f)
#define EPSV 1e-8f
#define FFT_N 8192

// ---------------- device scratch (static, no runtime alloc) ----------------
__device__ __nv_bfloat16 g_Et_hi[L * DE];   // E^T hi  ([l][e], e contiguous)
__device__ __nv_bfloat16 g_Et_lo[L * DE];
__device__ __nv_bfloat16 g_W_hi[DV * DE];   // W  ([v][e], e contiguous)
__device__ __nv_bfloat16 g_W_lo[DV * DE];
__device__ float g_Yt[(size_t)DV * L];      // Y^T fp32 ([v][l], l contiguous)
__device__ float g_outT[(size_t)DV * L];    // conv result [c][i]
__device__ float2 g_tw[FFT_N];              // exp(-2*pi*i*n/N), full table (W^{7u} max)
__device__ float2 g_F[FFT_N];               // FFT(f_padded)/N

// ---------------- helpers ---------------------------------------------------
__device__ __forceinline__ uint32_t smem_u32(const void* p) {
    uint32_t a;
    asm("{ .reg .u64 t; cvta.to.shared.u64 t, %1; cvt.u32.u64 %0, t; }" : "=r"(a) : "l"(p));
    return a;
}
#define SW64(o) ((uint32_t)(o) ^ ((((uint32_t)(o)) >> 3) & 0x30u))

__device__ __forceinline__ void cpasync16(uint32_t dst, const void* src) {
    asm volatile("cp.async.cg.shared.global [%0], [%1], 16;" :: "r"(dst), "l"(src));
}
#define CP_COMMIT() asm volatile("cp.async.commit_group;" ::: "memory")
#define CP_WAIT2()  asm volatile("cp.async.wait_group 2;" ::: "memory")

__device__ __forceinline__ void ldsm4(uint32_t* r, uint32_t addr) {
    asm volatile("ldmatrix.sync.aligned.m8n8.x4.shared.b16 {%0,%1,%2,%3}, [%4];"
                 : "=r"(r[0]), "=r"(r[1]), "=r"(r[2]), "=r"(r[3]) : "r"(addr));
}
__device__ __forceinline__ void mma_bf16(float* c, const uint32_t* a, const uint32_t* b) {
    asm volatile(
        "mma.sync.aligned.m16n8k16.row.col.f32.bf16.bf16.f32 "
        "{%0,%1,%2,%3}, {%4,%5,%6,%7}, {%8,%9}, {%0,%1,%2,%3};"
        : "+f"(c[0]), "+f"(c[1]), "+f"(c[2]), "+f"(c[3])
        : "r"(a[0]), "r"(a[1]), "r"(a[2]), "r"(a[3]), "r"(b[0]), "r"(b[1]));
}

__device__ __forceinline__ float2 cmul(float2 a, float2 b) {
    return make_float2(a.x * b.x - a.y * b.y, a.x * b.y + a.y * b.x);
}
__device__ __forceinline__ float2 cadd(float2 a, float2 b) { return make_float2(a.x + b.x, a.y + b.y); }
__device__ __forceinline__ float2 csub(float2 a, float2 b) { return make_float2(a.x - b.x, a.y - b.y); }

// ---------------- GEMM tiling: CTA 128x128, 4 warps (64x64 each), BK=32 -----
#define STAGE_BYTES 32768
#define T_AHI 0
#define T_ALO 8192
#define T_BHI 16384
#define T_BLO 24576
#define GEMM_SMEM (3 * STAGE_BYTES)

__device__ __forceinline__ void fill_tile32(uint32_t dstbase,
                                            const __nv_bfloat16* __restrict__ g,
                                            int row0, int k0, int stride, int tid) {
#pragma unroll
    for (int i = 0; i < 4; ++i) {
        int q = tid + i * 128;
        int r = q >> 2, c = q & 3;
        uint32_t o = (uint32_t)(r * 64 + c * 16);
        cpasync16(dstbase + SW64(o), g + (size_t)(row0 + r) * stride + k0 + c * 8);
    }
}

// ---------------- pre-kernels -----------------------------------------------
__global__ void init_tw_kernel() {
    int n = blockIdx.x * 256 + threadIdx.x;
    if (n < FFT_N) {
        float s, c;
        sincospif(-2.0f * (float)n / (float)FFT_N, &s, &c);
        g_tw[n] = make_float2(c, s);
    }
}

// E (e-major) -> Et hi/lo ([l][e]); tile 64e x 32l; bf16x2 stores
__global__ void transpose_E_kernel(const float* __restrict__ E) {
    __shared__ float t[64][33];
    int bx = blockIdx.x, by = blockIdx.y;          // bx: l-block(32), by: e-block(64)
    int tx = threadIdx.x, ty = threadIdx.y;        // block (32, 8)
#pragma unroll
    for (int i = 0; i < 8; ++i)
        t[ty + 8 * i][tx] = E[(size_t)(by * 64 + ty + 8 * i) * L + bx * 32 + tx];
    __syncthreads();
#pragma unroll
    for (int i = 0; i < 4; ++i) {
        int ll = ty + 8 * i;                       // local l 0..31
        float v0 = t[2 * tx][ll];
        float v1 = t[2 * tx + 1][ll];
        __nv_bfloat16 h0 = __float2bfloat16(v0);
        __nv_bfloat16 h1 = __float2bfloat16(v1);
        __nv_bfloat162 hp; hp.x = h0; hp.y = h1;
        __nv_bfloat162 lp;
        lp.x = __float2bfloat16(v0 - __bfloat162float(h0));
        lp.y = __float2bfloat16(v1 - __bfloat162float(h1));
        size_t o = (size_t)(bx * 32 + ll) * DE + by * 64 + 2 * tx;
        *reinterpret_cast<__nv_bfloat162*>(&g_Et_hi[o]) = hp;
        *reinterpret_cast<__nv_bfloat162*>(&g_Et_lo[o]) = lp;
    }
}

// float4 loads, 8 elems/thread
__global__ void convert_W_kernel(const float* __restrict__ W) {
    int base = (blockIdx.x * 256 + threadIdx.x) * 8;
#pragma unroll
    for (int h = 0; h < 2; ++h) {
        float4 v = *reinterpret_cast<const float4*>(&W[base + 4 * h]);
        float vv[4] = {v.x, v.y, v.z, v.w};
#pragma unroll
        for (int p = 0; p < 2; ++p) {
            __nv_bfloat16 h0 = __float2bfloat16(vv[2 * p]);
            __nv_bfloat16 h1 = __float2bfloat16(vv[2 * p + 1]);
            __nv_bfloat162 hp; hp.x = h0; hp.y = h1;
            __nv_bfloat162 lp;
            lp.x = __float2bfloat16(vv[2 * p] - __bfloat162float(h0));
            lp.y = __float2bfloat16(vv[2 * p + 1] - __bfloat162float(h1));
            int idx = base + 4 * h + 2 * p;
            *reinterpret_cast<__nv_bfloat162*>(&g_W_hi[idx]) = hp;
            *reinterpret_cast<__nv_bfloat162*>(&g_W_lo[idx]) = lp;
        }
    }
}

// ---------------- radix-8 Stockham FFT, skewed smem --------------------------
#define PHY(i) ((i) + ((i) >> 4))
#define FFT_BUF 8704
#define C_SQ2 0.70710678118654752f

// 4 radix-8 stages + 1 radix-2 stage; templated on thread count NT.
template <int NT, int MULT_F, int INV>
__device__ __forceinline__ void fft_stages8(float2* src0, float2* dst0, int tid) {
    float2* src = src0;
    float2* dst = dst0;
    int m = 1;
#pragma unroll 1
    for (int s = 0; s < 4; ++s) {
#pragma unroll
        for (int it = 0; it < 1024 / NT; ++it) {
            int bf = tid + it * NT;              // 0..1023
            int k = bf & (m - 1);
            int u = bf - k;
            float2 x0 = src[PHY(bf)];
            float2 x1 = src[PHY(bf + 1024)];
            float2 x2 = src[PHY(bf + 2048)];
            float2 x3 = src[PHY(bf + 3072)];
            float2 x4 = src[PHY(bf + 4096)];
            float2 x5 = src[PHY(bf + 5120)];
            float2 x6 = src[PHY(bf + 6144)];
            float2 x7 = src[PHY(bf + 7168)];
            float2 t0 = cadd(x0, x4), t1 = csub(x0, x4);
            float2 t2 = cadd(x2, x6), t3 = csub(x2, x6);
            float2 s0 = cadd(x1, x5), s1 = csub(x1, x5);
            float2 s2 = cadd(x3, x7), s3 = csub(x3, x7);
            float2 mjt3 = INV ? make_float2(-t3.y, t3.x) : make_float2(t3.y, -t3.x);
            float2 mjs3 = INV ? make_float2(-s3.y, s3.x) : make_float2(s3.y, -s3.x);
            float2 E0 = cadd(t0, t2), E2 = csub(t0, t2);
            float2 E1 = cadd(t1, mjt3), E3 = csub(t1, mjt3);
            float2 O0 = cadd(s0, s2), O2 = csub(s0, s2);
            float2 O1 = cadd(s1, mjs3), O3 = csub(s1, mjs3);
            float2 w1O1 = INV ? make_float2(C_SQ2 * (O1.x - O1.y), C_SQ2 * (O1.x + O1.y))
                              : make_float2(C_SQ2 * (O1.x + O1.y), C_SQ2 * (O1.y - O1.x));
            float2 w2O2 = INV ? make_float2(-O2.y, O2.x) : make_float2(O2.y, -O2.x);
            float2 w3O3 = INV ? make_float2(-C_SQ2 * (O3.x + O3.y), C_SQ2 * (O3.x - O3.y))
                              : make_float2(C_SQ2 * (O3.y - O3.x), -C_SQ2 * (O3.x + O3.y));
            float2 X[8];
            X[0] = cadd(E0, O0);   X[4] = csub(E0, O0);
            X[1] = cadd(E1, w1O1); X[5] = csub(E1, w1O1);
            X[2] = cadd(E2, w2O2); X[6] = csub(E2, w2O2);
            X[3] = cadd(E3, w3O3); X[7] = csub(E3, w3O3);
            int b8 = 8 * u + k;
            dst[PHY(b8)] = X[0];
#pragma unroll
            for (int j = 1; j < 8; ++j) {
                float2 w = g_tw[j * u];
                if (INV) w.y = -w.y;
                dst[PHY(b8 + j * m)] = cmul(w, X[j]);
            }
        }
        __syncthreads();
        float2* t = src; src = dst; dst = t;
        m <<= 3;
    }
#pragma unroll
    for (int it = 0; it < 4096 / NT; ++it) {
        int k = tid + it * NT;
        float2 a = src[PHY(k)];
        float2 b = src[PHY(k + FFT_N / 2)];
        float2 lo = cadd(a, b);
        float2 hi = csub(a, b);
        if (MULT_F) {
            lo = cmul(lo, g_F[k]);
            hi = cmul(hi, g_F[k + FFT_N / 2]);
        }
        dst[PHY(k)] = lo;
        dst[PHY(k + FFT_N / 2)] = hi;
    }
    __syncthreads();
}

__global__ __launch_bounds__(256) void fft_F_kernel() {
    extern __shared__ float2 sm[];
    float2* A = sm;
    float2* B = sm + FFT_BUF;
    int tid = threadIdx.x;
#pragma unroll
    for (int it = 0; it < 32; ++it) {
        int d = tid + it * 256;
        float v = 0.f;
        if (d < L) {
            float base = (d == 0) ? EPSV : ((float)d * DTF + EPSV);
            v = powf(base, HEXP);
        }
        A[PHY(d)] = make_float2(v, 0.f);
    }
    __syncthreads();
    fft_stages8<256, 0, 0>(A, B, tid);
    const float scale = 1.0f / (float)FFT_N;
#pragma unroll
    for (int it = 0; it < 32; ++it) {
        int n = tid + it * 256;
        float2 z = B[PHY(n)];
        g_F[n] = make_float2(z.x * scale, z.y * scale);
    }
}

#define CONV_NT 512
__global__ __launch_bounds__(CONV_NT) void conv_kernel() {
    extern __shared__ float2 sm[];
    float2* A = sm;
    float2* B = sm + FFT_BUF;
    int tid = threadIdx.x;
    int c2 = blockIdx.x * 2;
    const float* ya = g_Yt + (size_t)c2 * L;
    const float* yb = g_Yt + (size_t)(c2 + 1) * L;
#pragma unroll
    for (int it = 0; it < L / CONV_NT; ++it) {
        int i = tid + it * CONV_NT;
        A[PHY(i)] = make_float2(ya[i], yb[i]);
    }
#pragma unroll
    for (int it = 0; it < L / CONV_NT; ++it) {
        int i = L + tid + it * CONV_NT;
        A[PHY(i)] = make_float2(0.f, 0.f);
    }
    __syncthreads();
    fft_stages8<CONV_NT, 1, 0>(A, B, tid);   // forward + pointwise x F -> B
    fft_stages8<CONV_NT, 0, 1>(B, A, tid);   // inverse -> A
    float* oa = g_outT + (size_t)c2 * L;
    float* ob = g_outT + (size_t)(c2 + 1) * L;
#pragma unroll
    for (int it = 0; it < L / CONV_NT; ++it) {
        int i = tid + it * CONV_NT;
        float2 z = A[PHY(i)];
        oa[i] = z.x;
        ob[i] = z.y;
    }
}

// g_outT [c][i] -> out [i][c]; 64x64 tile, float2 both directions
__global__ void transpose_out_kernel(float* __restrict__ out) {
    __shared__ float2 t2[64][33];
    int i0 = blockIdx.x * 64, c0 = blockIdx.y * 64;
    int tx = threadIdx.x, ty = threadIdx.y;  // (32, 8)
#pragma unroll
    for (int k = 0; k < 8; ++k) {
        int r = ty + 8 * k;                  // local c
        t2[r][tx] = *reinterpret_cast<const float2*>(&g_outT[(size_t)(c0 + r) * L + i0 + 2 * tx]);
    }
    __syncthreads();
#pragma unroll
    for (int k = 0; k < 8; ++k) {
        int r = ty + 8 * k;                  // local i
        float2 p0 = t2[2 * tx][r >> 1];
        float2 p1 = t2[2 * tx + 1][r >> 1];
        float2 o;
        o.x = (r & 1) ? p0.y : p0.x;
        o.y = (r & 1) ? p1.y : p1.x;
        *reinterpret_cast<float2*>(&out[(size_t)(i0 + r) * DV + c0 + 2 * tx]) = o;
    }
}

// ---------------- GEMM1 compute core: warp tile 64x64 -----------------------
__device__ __forceinline__ void compute_stage64(uint32_t sbase, int lane, int wm, int wn,
                                                float acc[4][8][4]) {
    const int arow = lane & 15;
    const int acolb = (lane >> 4) << 4;
    const int brow = (lane & 7) + ((lane >> 4) << 3);
    const int bcolb = ((lane >> 3) & 1) << 4;
#pragma unroll
    for (int kk = 0; kk < 2; ++kk) {
        uint32_t aH[4][4], aL[4][4];
#pragma unroll
        for (int mi = 0; mi < 4; ++mi) {
            uint32_t o = SW64((uint32_t)((wm * 64 + mi * 16 + arow) * 64 + acolb)) ^ (kk << 5);
            ldsm4(aH[mi], sbase + T_AHI + o);
            ldsm4(aL[mi], sbase + T_ALO + o);
        }
#pragma unroll
        for (int pi = 0; pi < 4; ++pi) {
            uint32_t bH[4], bL[4];
            uint32_t o = SW64((uint32_t)((wn * 64 + pi * 16 + brow) * 64 + bcolb)) ^ (kk << 5);
            ldsm4(bH, sbase + T_BHI + o);
            ldsm4(bL, sbase + T_BLO + o);
#pragma unroll
            for (int mi = 0; mi < 4; ++mi)
#pragma unroll
                for (int q = 0; q < 2; ++q) {
                    mma_bf16(acc[mi][pi * 2 + q], aH[mi], &bH[q * 2]);
                    mma_bf16(acc[mi][pi * 2 + q], aH[mi], &bL[q * 2]);
                    mma_bf16(acc[mi][pi * 2 + q], aL[mi], &bH[q * 2]);
                }
        }
    }
}

// ---------------- GEMM1: Yt[v][l] = sum_e W[v][e] * Et[l][e] ----------------
__global__ __launch_bounds__(128, 2) void gemm1_mma() {
    extern __shared__ char smem[];
    const uint32_t sb = smem_u32(smem);
    const int tid = threadIdx.x, lane = tid & 31, wid = tid >> 5;
    const int wm = wid & 1, wn = (wid >> 1) & 1;
    const int l0 = blockIdx.x * 128;
    const int v0 = blockIdx.y * 128;
    const int KT = DE / 32;

    float acc[4][8][4];
#pragma unroll
    for (int mi = 0; mi < 4; ++mi)
#pragma unroll
        for (int ni = 0; ni < 8; ++ni)
#pragma unroll
            for (int r = 0; r < 4; ++r) acc[mi][ni][r] = 0.f;

#pragma unroll
    for (int s = 0; s < 2; ++s) {
        uint32_t st = sb + s * STAGE_BYTES;
        int k0 = s * 32;
        fill_tile32(st + T_AHI, g_W_hi, v0, k0, DE, tid);
        fill_tile32(st + T_ALO, g_W_lo, v0, k0, DE, tid);
        fill_tile32(st + T_BHI, g_Et_hi, l0, k0, DE, tid);
        fill_tile32(st + T_BLO, g_Et_lo, l0, k0, DE, tid);
        CP_COMMIT();
    }
    for (int kt = 0; kt < KT; ++kt) {
        int ls = kt + 2;
        if (ls < KT) {
            uint32_t st = sb + (ls % 3) * STAGE_BYTES;
            int k0 = ls * 32;
            fill_tile32(st + T_AHI, g_W_hi, v0, k0, DE, tid);
            fill_tile32(st + T_ALO, g_W_lo, v0, k0, DE, tid);
            fill_tile32(st + T_BHI, g_Et_hi, l0, k0, DE, tid);
            fill_tile32(st + T_BLO, g_Et_lo, l0, k0, DE, tid);
        }
        CP_COMMIT();
        CP_WAIT2();
        __syncthreads();
        compute_stage64(sb + (kt % 3) * STAGE_BYTES, lane, wm, wn, acc);
        __syncthreads();
    }

#pragma unroll
    for (int mi = 0; mi < 4; ++mi)
#pragma unroll
        for (int ni = 0; ni < 8; ++ni) {
            const float* c = acc[mi][ni];
            int v_ = v0 + wm * 64 + mi * 16 + (lane >> 2);
            int l_ = l0 + wn * 64 + ni * 8 + 2 * (lane & 3);
#pragma unroll
            for (int h = 0; h < 2; ++h) {
                float2 p;
                p.x = c[2 * h];
                p.y = c[2 * h + 1];
                *reinterpret_cast<float2*>(&g_Yt[(size_t)(v_ + 8 * h) * L + l_]) = p;
            }
        }
}

// ---------------------------------------------------------------------------
#define FFT_SMEM (2 * FFT_BUF * (int)sizeof(float2))

extern "C" void kernel_launch(void* const* d_in, const int* in_sizes, int n_in,
                              void* d_out, int out_size) {
    const float* E = (const float*)d_in[0];   // (1024, 4096)
    const float* W = (const float*)d_in[1];   // (1024, 1024)
    float* out = (float*)d_out;               // (4096, 1024)

    cudaFuncSetAttribute(gemm1_mma, cudaFuncAttributeMaxDynamicSharedMemorySize, GEMM_SMEM);
    cudaFuncSetAttribute(fft_F_kernel, cudaFuncAttributeMaxDynamicSharedMemorySize, FFT_SMEM);
    cudaFuncSetAttribute(conv_kernel, cudaFuncAttributeMaxDynamicSharedMemorySize, FFT_SMEM);

    init_tw_kernel<<<FFT_N / 256, 256>>>();
    fft_F_kernel<<<1, 256, FFT_SMEM>>>();
    transpose_E_kernel<<<dim3(L / 32, DE / 64), dim3(32, 8)>>>(E);
    convert_W_kernel<<<(DV * DE) / (256 * 8), 256>>>(W);
    gemm1_mma<<<dim3(L / 128, DV / 128), 128, GEMM_SMEM>>>();
    conv_kernel<<<DV / 2, CONV_NT, FFT_SMEM>>>();
    transpose_out_kernel<<<dim3(L / 64, DV / 64), dim3(32, 8)>>>(out);
}